// round 8
// baseline (speedup 1.0000x reference)
#include <cuda_runtime.h>
#include <cuda_bf16.h>
#include <cstdint>
#include <math.h>

#define N_ROWS 2048
#define DIM    512
#define K_NEG  65536
#define TEMP   0.2f
#define EPSV   1e-8f
#define LOG2E  1.4426950408889634f

// GEMM tiling
#define BM 128
#define BN 128
#define KC 128                 // K per pipeline chunk (fp8 bytes)
#define NCHT 4                 // chunks per tile (DIM/KC)
#define NNB (K_NEG / BN)       // 512 n-blocks
#define YCTAS 9                // 16*9 = 144 CTAs = 1 wave
#define NPART (YCTAS * 4)      // 36 partials per row (one per (y, wn))

// SMEM layout (conflict-free pad strides: stride/4 mod 32 == 4)
#define ASTR 528u              // bytes per A row (512 + 16)
#define BSTR 144u              // bytes per B row (128 + 16)
#define A_BYTES   (128u * ASTR)          // 67584
#define B_STAGE   (128u * BSTR)          // 18432
#define OFF_A     0u
#define OFF_B     A_BYTES
#define OFF_CS    (OFF_B + 4u * B_STAGE) // 141312 (2 x 512B cs buffers)
#define SMEM_TOTAL (OFF_CS + 1024u)      // 142336

// Scratch
__device__ uint8_t g_qf8[N_ROWS * DIM];
__device__ uint8_t g_uf8[(size_t)K_NEG * DIM];
__device__ float g_rowscale[N_ROWS];   // log2e / (||q||*T)
__device__ float g_lpos[N_ROWS];
__device__ float g_colscale[K_NEG];    // 1/||u||
__device__ float g_part[N_ROWS * NPART];
__device__ float g_rowloss[N_ROWS];

// ---------------- helpers ----------------
__device__ __forceinline__ uint32_t smem_u32(const void* p) {
    uint32_t a;
    asm("{ .reg .u64 t; cvta.to.shared.u64 t, %1; cvt.u32.u64 %0, t; }" : "=r"(a) : "l"(p));
    return a;
}
__device__ __forceinline__ void cp16(uint32_t sp, const void* gp) {
    asm volatile("cp.async.cg.shared.global [%0], [%1], 16;\n" :: "r"(sp), "l"(gp));
}
__device__ __forceinline__ float ex2f(float x) {
    float r;
    asm("ex2.approx.ftz.f32 %0, %1;" : "=f"(r) : "f"(x));
    return r;
}
// pack 2 fp32 -> e4m3x2 (first src -> high byte)
__device__ __forceinline__ uint16_t f2e4m3x2(float hi, float lo) {
    uint16_t r;
    asm("cvt.rn.satfinite.e4m3x2.f32 %0, %1, %2;" : "=h"(r) : "f"(hi), "f"(lo));
    return r;
}
__device__ __forceinline__ void mma_fp8(float* c, const uint32_t* a, const uint32_t* b) {
    asm volatile(
        "mma.sync.aligned.m16n8k32.row.col.f32.e4m3.e4m3.f32 "
        "{%0,%1,%2,%3}, {%4,%5,%6,%7}, {%8,%9}, {%0,%1,%2,%3};\n"
        : "+f"(c[0]), "+f"(c[1]), "+f"(c[2]), "+f"(c[3])
        : "r"(a[0]), "r"(a[1]), "r"(a[2]), "r"(a[3]), "r"(b[0]), "r"(b[1]));
}
__device__ __forceinline__ void ldsm4(uint32_t* r, uint32_t addr) {
    asm volatile("ldmatrix.sync.aligned.m8n8.x4.shared.b16 {%0,%1,%2,%3}, [%4];\n"
                 : "=r"(r[0]), "=r"(r[1]), "=r"(r[2]), "=r"(r[3]) : "r"(addr));
}

// ---------------------------------------------------------------------------
// Kernel 1: query/keys norms, l_pos (fp32-exact), fp8 convert of query
// ---------------------------------------------------------------------------
__global__ void prep_qk(const float* __restrict__ q, const float* __restrict__ k) {
    int r = blockIdx.x;
    int tid = threadIdx.x;   // 256
    const float* qr = q + r * DIM;
    const float* kr = k + r * DIM;
    float sq, sk, dp;
    {   // 2 elems per thread
        int d = tid * 2;
        float q0 = qr[d], q1 = qr[d + 1];
        float k0 = kr[d], k1 = kr[d + 1];
        sq = q0 * q0 + q1 * q1;
        sk = k0 * k0 + k1 * k1;
        dp = q0 * k0 + q1 * k1;
        ((uint16_t*)g_qf8)[(r * DIM + d) >> 1] = f2e4m3x2(q1, q0);
    }
    #pragma unroll
    for (int o = 16; o; o >>= 1) {
        sq += __shfl_xor_sync(0xffffffffu, sq, o);
        sk += __shfl_xor_sync(0xffffffffu, sk, o);
        dp += __shfl_xor_sync(0xffffffffu, dp, o);
    }
    __shared__ float s1[8], s2[8], s3[8];
    int w = tid >> 5;
    if ((tid & 31) == 0) { s1[w] = sq; s2[w] = sk; s3[w] = dp; }
    __syncthreads();
    if (tid == 0) {
        float a = 0.f, b = 0.f, c = 0.f;
        for (int i = 0; i < 8; i++) { a += s1[i]; b += s2[i]; c += s3[i]; }
        float qn = sqrtf(a), kn = sqrtf(b);
        g_rowscale[r] = LOG2E / (qn * TEMP);
        g_lpos[r] = c / fmaxf(qn * kn, EPSV) / TEMP;
    }
}

// ---------------------------------------------------------------------------
// Kernel 2: queue norms + fp8 convert (float4 reads, uint32 fp8 writes)
// ---------------------------------------------------------------------------
__global__ void prep_u(const float* __restrict__ u) {
    int r = blockIdx.x;
    int tid = threadIdx.x;   // 128
    const float4* ur = (const float4*)(u + (size_t)r * DIM);
    float4 v = ur[tid];
    float su = v.x * v.x + v.y * v.y + v.z * v.z + v.w * v.w;
    uint32_t lo = f2e4m3x2(v.y, v.x);
    uint32_t hi = f2e4m3x2(v.w, v.z);
    ((uint32_t*)g_uf8)[((size_t)r * DIM >> 2) + tid] = (hi << 16) | lo;
    #pragma unroll
    for (int o = 16; o; o >>= 1) su += __shfl_xor_sync(0xffffffffu, su, o);
    __shared__ float s1[4];
    int w = tid >> 5;
    if ((tid & 31) == 0) s1[w] = su;
    __syncthreads();
    if (tid == 0) g_colscale[r] = rsqrtf(s1[0] + s1[1] + s1[2] + s1[3]);
}

// ---------------------------------------------------------------------------
// Kernel 3: persistent fp8 mma.sync GEMM + fused exp2/row-sum epilogue.
// Grid (16, 9). CTA (mb, y): A[mb] resident in SMEM; streams n-blocks
// y, y+9, ... 4-deep cp.async chunk ring. Fragments via ldmatrix.x4.
// Warps: 2(m) x 4(n), warp tile 64x32, mma m16n8k32 e4m3.
// ---------------------------------------------------------------------------
__global__ void __launch_bounds__(256) gemm_lse() {
    extern __shared__ __align__(128) char smem[];
    const uint32_t sb = smem_u32(smem);
    const int tid = threadIdx.x;
    const int lane = tid & 31;
    const int wid = tid >> 5;
    const int wm = wid >> 2;       // 0..1
    const int wn = wid & 3;        // 0..3
    const int g = lane >> 2;       // 0..7
    const int t = lane & 3;        // 0..3
    const int mb = blockIdx.x;
    const int y = blockIdx.y;

    // Resident A: 128 rows x 512B, pad stride 528
    {
        const uint8_t* gA = g_qf8 + (size_t)mb * BM * DIM;
        #pragma unroll
        for (int i = 0; i < 16; i++) {
            int s = tid + i * 256;
            int r = s >> 5, s8 = s & 31;
            cp16(sb + OFF_A + r * ASTR + s8 * 16, gA + (size_t)r * DIM + s8 * 16);
        }
        asm volatile("cp.async.commit_group;\n");
    }

    // Per-thread row scales (8 rows: 4 m-tiles x 2 halves), log2e/T folded in
    float rs[8];
    #pragma unroll
    for (int i = 0; i < 4; i++)
        #pragma unroll
        for (int h = 0; h < 2; h++)
            rs[i * 2 + h] = g_rowscale[mb * BM + wm * 64 + i * 16 + h * 8 + g];

    // ldmatrix base addresses.
    // A (per m-tile i, x4 = {row g, ka}, {row g+8, ka}, {row g, ka+16}, {row g+8, ka+16}):
    //   lanes 0-15 -> row (lane&15) @ +0 ; lanes 16-31 -> row (lane&15) @ +16
    uint32_t aaddr[4];
    #pragma unroll
    for (int i = 0; i < 4; i++)
        aaddr[i] = sb + OFF_A + (wm * 64 + i * 16 + (lane & 15)) * ASTR
                 + ((lane >> 4) * 16);
    // B (per j-pair jp, x4 = {n0 rows, kb}, {n0, kb+16}, {n0+8, kb}, {n0+8, kb+16}):
    //   row = wn*32 + jp*16 + ((lane>>4)&1)*8 + (lane&7); byte = ((lane>>3)&1)*16
    uint32_t baddr[2];
    #pragma unroll
    for (int jp = 0; jp < 2; jp++)
        baddr[jp] = sb + OFF_B
                  + (wn * 32 + jp * 16 + ((lane >> 4) & 1) * 8 + (lane & 7)) * BSTR
                  + (((lane >> 3) & 1) * 16);

    const int ntiles = (NNB - 1 - y) / YCTAS + 1;   // 56 or 57
    const int total = ntiles * NCHT;

    // chunk issue: stream s -> tile s>>2, chunk s&3, stage s&3
    auto issue = [&](int s) {
        if (s >= total) return;
        int tt = s >> 2, c = s & 3;
        int nb = y + tt * YCTAS;
        if (c == 0 && tid < 32) {  // colscale for this tile (ping-pong by tile parity)
            cp16(sb + OFF_CS + (uint32_t)(tt & 1) * 512 + tid * 16,
                 g_colscale + nb * BN + tid * 4);
        }
        const uint8_t* gB = g_uf8 + (size_t)nb * BN * DIM + c * KC;
        uint32_t bb = sb + OFF_B + (uint32_t)c * B_STAGE;
        #pragma unroll
        for (int i = 0; i < 4; i++) {
            int ss = tid + i * 256;
            int r = ss >> 3, s8 = ss & 7;
            cp16(bb + r * BSTR + s8 * 16, gB + (size_t)r * DIM + s8 * 16);
        }
        asm volatile("cp.async.commit_group;\n");
    };

    issue(0); issue(1); issue(2);

    float acc[4][4][4];
    #pragma unroll
    for (int i = 0; i < 4; i++)
        #pragma unroll
        for (int j = 0; j < 4; j++)
            #pragma unroll
            for (int v = 0; v < 4; v++) acc[i][j][v] = 0.f;
    float rsum[8];
    #pragma unroll
    for (int i = 0; i < 8; i++) rsum[i] = 0.f;

    #pragma unroll 1
    for (int s = 0; s < total; s++) {
        const int c = s & 3;
        asm volatile("cp.async.wait_group 2;\n");
        __syncthreads();
        issue(s + 3);

        // consume chunk c (stage c): 4 k32 steps, fragments via ldmatrix
        const uint32_t acol = (uint32_t)(c * KC);
        const uint32_t bstg = (uint32_t)c * B_STAGE;
        #pragma unroll
        for (int st = 0; st < 4; st++) {
            const uint32_t ka = acol + st * 32;
            const uint32_t kb = bstg + st * 32;
            uint32_t b[4][2];
            ldsm4(&b[0][0], baddr[0] + kb);   // -> b[0][0],b[0][1],b[1][0],b[1][1]
            ldsm4(&b[2][0], baddr[1] + kb);   // -> b[2][0],b[2][1],b[3][0],b[3][1]
            #pragma unroll
            for (int i = 0; i < 4; i++) {
                uint32_t a[4];
                ldsm4(a, aaddr[i] + ka);      // a0..a3 fragment for this m-tile
                #pragma unroll
                for (int j = 0; j < 4; j++) mma_fp8(acc[i][j], a, b[j]);
            }
        }

        if (c == 3) {   // tile complete: exp2 + accumulate row sums, reset accs
            const uint32_t csb = sb + OFF_CS + (uint32_t)((s >> 2) & 1) * 512;
            #pragma unroll
            for (int j = 0; j < 4; j++) {
                float2 cs;
                asm volatile("ld.shared.v2.f32 {%0,%1}, [%2];"
                             : "=f"(cs.x), "=f"(cs.y)
                             : "r"(csb + (uint32_t)(wn * 32 + j * 8 + 2 * t) * 4));
                #pragma unroll
                for (int i = 0; i < 4; i++) {
                    float r0 = rs[i * 2 + 0], r1 = rs[i * 2 + 1];
                    rsum[i * 2 + 0] += ex2f(acc[i][j][0] * r0 * cs.x)
                                     + ex2f(acc[i][j][1] * r0 * cs.y);
                    rsum[i * 2 + 1] += ex2f(acc[i][j][2] * r1 * cs.x)
                                     + ex2f(acc[i][j][3] * r1 * cs.y);
                    acc[i][j][0] = 0.f; acc[i][j][1] = 0.f;
                    acc[i][j][2] = 0.f; acc[i][j][3] = 0.f;
                }
            }
        }
    }

    // reduce over quad (t) and write one partial per (row, y, wn)
    #pragma unroll
    for (int i = 0; i < 8; i++) {
        rsum[i] += __shfl_xor_sync(0xffffffffu, rsum[i], 1);
        rsum[i] += __shfl_xor_sync(0xffffffffu, rsum[i], 2);
    }
    if (t == 0) {
        #pragma unroll
        for (int i = 0; i < 4; i++)
            #pragma unroll
            for (int h = 0; h < 2; h++) {
                int row = mb * BM + wm * 64 + i * 16 + h * 8 + g;
                g_part[(size_t)row * NPART + y * 4 + wn] = rsum[i * 2 + h];
            }
    }
}

// ---------------------------------------------------------------------------
// Kernel 4: per-row reduce of 36 partials -> rowloss = lse - l_pos
// 4 rows per block (warp per row).
// ---------------------------------------------------------------------------
__global__ void reduce_row() {
    int r = blockIdx.x * 4 + (threadIdx.x >> 5);
    int lt = threadIdx.x & 31;
    float s = 0.f;
    for (int i = lt; i < NPART; i += 32) s += g_part[(size_t)r * NPART + i];
    #pragma unroll
    for (int o = 16; o; o >>= 1) s += __shfl_xor_sync(0xffffffffu, s, o);
    if (lt == 0) {
        float lp = g_lpos[r];
        s += expf(lp);                 // positive logit term
        g_rowloss[r] = logf(s) - lp;   // |logit|<=~6 -> no max subtraction needed
    }
}

// ---------------------------------------------------------------------------
// Kernel 5: mean over rows -> output scalar
// ---------------------------------------------------------------------------
__global__ void finalize(float* __restrict__ out) {
    int tid = threadIdx.x;
    float s = 0.f;
    for (int i = tid; i < N_ROWS; i += blockDim.x) s += g_rowloss[i];
    #pragma unroll
    for (int o = 16; o; o >>= 1) s += __shfl_xor_sync(0xffffffffu, s, o);
    __shared__ float sw[32];
    int w = tid >> 5;
    if ((tid & 31) == 0) sw[w] = s;
    __syncthreads();
    if (tid == 0) {
        float tot = 0.f;
        int nw = blockDim.x >> 5;
        for (int i = 0; i < nw; i++) tot += sw[i];
        out[0] = tot / (float)N_ROWS;
    }
}

// ---------------------------------------------------------------------------
extern "C" void kernel_launch(void* const* d_in, const int* in_sizes, int n_in,
                              void* d_out, int out_size) {
    const float* query = (const float*)d_in[0];
    const float* keys  = (const float*)d_in[1];
    const float* queue = (const float*)d_in[2];
    float* out = (float*)d_out;

    cudaFuncSetAttribute(gemm_lse, cudaFuncAttributeMaxDynamicSharedMemorySize, SMEM_TOTAL);

    prep_qk<<<N_ROWS, 256>>>(query, keys);
    prep_u<<<K_NEG, 128>>>(queue);
    gemm_lse<<<dim3(N_ROWS / BM, YCTAS), 256, SMEM_TOTAL>>>();
    reduce_row<<<N_ROWS / 4, 128>>>();
    finalize<<<1, 1024>>>(out);
}